// round 17
// baseline (speedup 1.0000x reference)
#include <cuda_runtime.h>
#include <cuda_fp16.h>
#include <cstdint>

// AdaptiveSample (R16 + interleaved uint4 tap layout: 1 LDS.128 serves 8 channels):
//   weights: softmax over 15 sampled taps of valid*posw*guide (fp32, R16-identical)
//   gather:  2 phases x 16 channels; per phase 2 groups of 4 channel-pairs
//            interleaved per pixel (uint4 = 8 ch); per tap: 1 LDS.128 + 4 HFMA2,
//            fp32 flush every 8 taps (accumulation order identical to R16)
//   copy:    features passthrough gmem->gmem float4 (bit-exact).

namespace {
constexpr int H  = 256;
constexpr int W  = 512;
constexpr int C  = 32;
constexpr int B  = 2;
constexpr int S  = 15;
constexpr int KS = 5;
constexpr int KK = 25;
constexpr int HW = H * W;

constexpr int BW = 32;            // tile width (warp-coalesced)
constexpr int BH = 8;             // tile height
constexpr int NT = BW * BH;       // 256 threads

constexpr int FP   = 48;          // halo pitch (px): cols [w0-8, w0+40)
constexpr int FR   = 12;          // halo rows: [h0-2, h0+10)
constexpr int SLOT = FP * FR;     // 576 px per tile
constexpr int PC   = 16;          // channels per phase
constexpr int NP   = C / PC;      // 2 phases
constexpr int NGRP = 2;           // groups of 8 channels per phase
constexpr int GBUF = BH * BW * KK;  // guide floats (6400=25.6KB); feature buf needs
                                    // 2 groups * 576 px * 16B = 18432B (aliased)
}

__device__ __forceinline__ float getc(float4 v, int k) {
    return k == 0 ? v.x : (k == 1 ? v.y : (k == 2 ? v.z : v.w));
}

__global__ __launch_bounds__(NT, 5)
void adaptive_sample_kernel(const float* __restrict__ depth,
                            const float* __restrict__ features,
                            const float* __restrict__ guide,
                            const int*   __restrict__ sidx,
                            float* __restrict__ out,
                            float* __restrict__ outf,
                            int do_copy)
{
    __shared__ alignas(16) float shbuf[GBUF];   // guide tile, then uint4 feature tiles
    __shared__ float       sh_posw[S];
    __shared__ int         sh_k[S];
    __shared__ signed char sh_dy[S], sh_dx[S];

    const int tx  = threadIdx.x;
    const int ty  = threadIdx.y;
    const int tid = ty * BW + tx;
    const int w0  = blockIdx.x * BW;
    const int h0  = blockIdx.y * BH;
    const int b   = blockIdx.z;

    // ---- tap metadata (one thread; S=15 trivial) ----
    if (tid == 0) {
        float pw[S];
        float sum = 0.f;
        #pragma unroll
        for (int s = 0; s < S; ++s) {
            int k  = sidx[s];
            int px = k % KS;
            int py = k / KS;
            float fx = (float)px - 2.f;
            float fy = (float)py - 2.f;
            float v  = __expf(-0.5f * sqrtf(fx * fx + fy * fy));
            pw[s] = v; sum += v;
            sh_k[s]  = k;
            sh_dy[s] = (signed char)(py - 2);
            sh_dx[s] = (signed char)(px - 2);
        }
        float inv = 1.f / sum;
        #pragma unroll
        for (int s = 0; s < S; ++s) sh_posw[s] = pw[s] * inv;
    }

    // ---- stage guide tile (contiguous float4 rows; R16-identical) ----
    #pragma unroll
    for (int it = 0; it < (GBUF / 4 + NT - 1) / NT; ++it) {
        int i4 = tid + it * NT;
        if (i4 < GBUF / 4) {
            int row = i4 / (BW * KK / 4);
            int in4 = i4 - row * (BW * KK / 4);
            const float4* src = reinterpret_cast<const float4*>(
                guide + (((size_t)b * H + (h0 + row)) * W + w0) * KK) + in4;
            reinterpret_cast<float4*>(shbuf + row * BW * KK)[in4] = *src;
        }
    }
    __syncthreads();

    const int h = h0 + ty;
    const int w = w0 + tx;

    // ---- per-pixel softmax weights (fp32) -> half2 broadcast regs + pixel indices ----
    const float* drow = depth + (size_t)b * HW;
    const float* gpix = shbuf + (ty * BW + tx) * KK;   // lane stride 25: conflict-free

    __half2 hwv[S];     // (w_s, w_s)
    int     pidx[S];    // tap pixel index within the halo tile
    {
        float    wv[S];
        unsigned ibm  = 0u;
        float    gmax = 0.f;  // logits >= 0
        #pragma unroll
        for (int s = 0; s < S; ++s) {
            int dy = (int)sh_dy[s], dx = (int)sh_dx[s];
            int hh = h + dy, ww = w + dx;
            bool ib = ((unsigned)hh < (unsigned)H) && ((unsigned)ww < (unsigned)W);
            float d = ib ? __ldg(drow + hh * W + ww) : 0.f;
            bool valid = ib && (d > 0.f) && (d < 192.0f);
            float logit = valid ? sh_posw[s] * gpix[sh_k[s]] : 0.f;
            wv[s] = logit;
            gmax  = fmaxf(gmax, logit);
            ibm  |= (unsigned)ib << s;
            pidx[s] = (ty + 2 + dy) * FP + (tx + 8 + dx);
        }
        float esum = 0.f;
        #pragma unroll
        for (int s = 0; s < S; ++s) { wv[s] = __expf(wv[s] - gmax); esum += wv[s]; }
        float inv = 1.f / esum;
        #pragma unroll
        for (int s = 0; s < S; ++s) {
            float ws = ((ibm >> s) & 1u) ? wv[s] * inv : 0.f;  // OOB tap == zero-pad
            hwv[s] = __half2half2(__float2half_rn(ws));
        }
    }

    __syncthreads();  // guide reads done; shbuf becomes interleaved feature buffer

    uint4* qbuf = reinterpret_cast<uint4*>(shbuf);   // [group][pixel] -> 8 channels

    const float* fbase = features + (size_t)b * C * HW;
    float*       obase = out + (size_t)b * C * HW + (size_t)h * W + w;

    #pragma unroll
    for (int ph = 0; ph < NP; ++ph) {
        const int c0 = ph * PC;

        // ---- stage: unit = 8 channels x 4 px -> 8 LDG.128 + 16 cvt + 4 STS.128 ----
        #pragma unroll
        for (int it = 0; it < 2; ++it) {                    // 288 units / 256 thr
            int i = tid + it * NT;
            if (i < NGRP * FR * (FP / 4)) {
                int g   = i / (FR * FP / 4);                // /144
                int rem = i - g * (FR * FP / 4);
                int r   = rem / (FP / 4);                   // /12
                int q   = rem - r * (FP / 4);
                int gh  = min(max(h0 + r - 2, 0), H - 1);
                int gc  = min(max(w0 - 8 + q * 4, 0), W - 4);
                const float* src = fbase + (size_t)(c0 + g * 8) * HW + gh * W + gc;
                float4 v[8];
                #pragma unroll
                for (int j = 0; j < 8; ++j)
                    v[j] = __ldg(reinterpret_cast<const float4*>(src + (size_t)j * HW));
                #pragma unroll
                for (int k = 0; k < 4; ++k) {
                    __half2 p0 = __floats2half2_rn(getc(v[0], k), getc(v[1], k));
                    __half2 p1 = __floats2half2_rn(getc(v[2], k), getc(v[3], k));
                    __half2 p2 = __floats2half2_rn(getc(v[4], k), getc(v[5], k));
                    __half2 p3 = __floats2half2_rn(getc(v[6], k), getc(v[7], k));
                    uint4 u;
                    u.x = *reinterpret_cast<uint32_t*>(&p0);
                    u.y = *reinterpret_cast<uint32_t*>(&p1);
                    u.z = *reinterpret_cast<uint32_t*>(&p2);
                    u.w = *reinterpret_cast<uint32_t*>(&p3);
                    qbuf[g * SLOT + r * FP + q * 4 + k] = u;
                }
            }
        }
        __syncthreads();

        // ---- hot loop: per group, 15 x (1 LDS.128 + 4 HFMA2); fp32 flush at s=7,14 ----
        #pragma unroll
        for (int g = 0; g < NGRP; ++g) {
            const uint4* gp = qbuf + g * SLOT;
            float2  f0 = {0.f, 0.f}, f1 = {0.f, 0.f}, f2 = {0.f, 0.f}, f3 = {0.f, 0.f};
            __half2 a0 = __half2half2(__ushort_as_half(0)),
                    a1 = a0, a2 = a0, a3 = a0;
            #pragma unroll
            for (int s = 0; s < S; ++s) {
                uint4 u = gp[pidx[s]];
                __half2 wt = hwv[s];
                a0 = __hfma2(*reinterpret_cast<__half2*>(&u.x), wt, a0);
                a1 = __hfma2(*reinterpret_cast<__half2*>(&u.y), wt, a1);
                a2 = __hfma2(*reinterpret_cast<__half2*>(&u.z), wt, a2);
                a3 = __hfma2(*reinterpret_cast<__half2*>(&u.w), wt, a3);
                if (s == 7) {   // mid flush keeps half partials small
                    float2 t;
                    t = __half22float2(a0); f0.x += t.x; f0.y += t.y;
                    t = __half22float2(a1); f1.x += t.x; f1.y += t.y;
                    t = __half22float2(a2); f2.x += t.x; f2.y += t.y;
                    t = __half22float2(a3); f3.x += t.x; f3.y += t.y;
                    a0 = a1 = a2 = a3 = __half2half2(__ushort_as_half(0));
                }
            }
            float2 t;
            t = __half22float2(a0); f0.x += t.x; f0.y += t.y;
            t = __half22float2(a1); f1.x += t.x; f1.y += t.y;
            t = __half22float2(a2); f2.x += t.x; f2.y += t.y;
            t = __half22float2(a3); f3.x += t.x; f3.y += t.y;

            const int cb = c0 + g * 8;
            obase[(size_t)(cb + 0) * HW] = f0.x;
            obase[(size_t)(cb + 1) * HW] = f0.y;
            obase[(size_t)(cb + 2) * HW] = f1.x;
            obase[(size_t)(cb + 3) * HW] = f1.y;
            obase[(size_t)(cb + 4) * HW] = f2.x;
            obase[(size_t)(cb + 5) * HW] = f2.y;
            obase[(size_t)(cb + 6) * HW] = f3.x;
            obase[(size_t)(cb + 7) * HW] = f3.y;
        }
        __syncthreads();
    }

    // ---- passthrough copy, gmem->gmem float4 (bit-exact; tile is L2-hot) ----
    if (do_copy) {
        float* ocbase = outf + (size_t)b * C * HW;
        #pragma unroll
        for (int it = 0; it < (C * BH * BW / 4) / NT; ++it) {   // 8
            int i   = tid + it * NT;
            int c   = i >> 6;
            int rem = i & 63;
            int r   = rem >> 3;
            int q4  = rem & 7;
            size_t off = (size_t)c * HW + (size_t)(h0 + r) * W + w0 + q4 * 4;
            float4 v = __ldg(reinterpret_cast<const float4*>(fbase + off));
            *reinterpret_cast<float4*>(ocbase + off) = v;
        }
    }
}

extern "C" void kernel_launch(void* const* d_in, const int* in_sizes, int n_in,
                              void* d_out, int out_size)
{
    const float* depth    = (const float*)d_in[0];
    const float* features = (const float*)d_in[1];
    const float* guide    = (const float*)d_in[2];
    const int*   sidx     = (const int*)d_in[3];

    float* out = (float*)d_out;
    const int featN = in_sizes[1];                       // B*C*H*W
    const int do_copy = (out_size >= 2 * featN) ? 1 : 0; // tuple output: (out, features)
    float* outf = out + featN;

    dim3 block(BW, BH);
    dim3 grid(W / BW, H / BH, B);
    adaptive_sample_kernel<<<grid, block>>>(depth, features, guide, sidx,
                                            out, outf, do_copy);
}